// round 1
// baseline (speedup 1.0000x reference)
#include <cuda_runtime.h>

// STCA loss, single-pass streaming formulation.
// Traces: B*N = 32768, each T=2048 fp32. Per trace we need:
//   - num_clusters (spike runs with gaps <= C=3 merged)
//   - smallest cluster's (sum of v>0, count of v>0)  [ties -> first cluster]
//   - max(v) over the trace
// Loss = sum over (b,n):
//   label & no cluster      -> -max(v)
//   ~label & has cluster    ->  possum / max(poscount,1)
// Output: d_out[0] = loss, d_out[1 + r] = num_clusters(r) as float.

#define B_DIM 128
#define N_DIM 256
#define T_DIM 2048
#define C_GAP 3

#define TPB   64                      // traces per block (= threads per block)
#define TT    32                      // timesteps per tile
#define NTILE (T_DIM / TT)            // 64
#define PITCH 36                      // floats per smem row: 16B-aligned rows, conflict-friendly
#define NBLOCKS ((B_DIM * N_DIM) / TPB)  // 512

__device__ float g_partial[NBLOCKS];

__device__ __forceinline__ void proc_step(
    float v, int t,
    float& vmax, int& last, int& nclust,
    int& curc, float& cursum, int& curcnt,
    int& bestc, float& bestsum, int& bestcnt)
{
    vmax = fmaxf(vmax, v);
    if (v >= 0.0f) {                       // spike
        if (t - last > C_GAP) {            // new cluster: close previous, open new
            if (curc < bestc) { bestc = curc; bestsum = cursum; bestcnt = curcnt; }
            curc = 0; cursum = 0.0f; curcnt = 0;
            nclust++;
        }
        curc++;
        if (v > 0.0f) { cursum += v; curcnt++; }
        last = t;
    }
}

__global__ void __launch_bounds__(TPB)
stca_scan(const float* __restrict__ vmem,
          const int*   __restrict__ labels,
          float*       __restrict__ out_spike)   // = d_out + 1
{
    __shared__ float sh[2][TPB][PITCH];
    __shared__ float red[TPB];

    const int tid       = threadIdx.x;
    const int traceBase = blockIdx.x * TPB;
    const int myTrace   = traceBase + tid;

    // Cooperative-load mapping: 64 traces x 32 timesteps = 512 float4 per tile.
    // Thread -> (tq = float4 column 0..7, trl0 = trace 0..7), k loop covers +8k traces.
    // Consecutive 8 lanes read 128B contiguous per trace row -> fully coalesced.
    const int tq   = tid & 7;
    const int trl0 = tid >> 3;

    const float4* __restrict__ g4 = reinterpret_cast<const float4*>(vmem);

    float4 stage[8];

    // Prologue: load tile 0
    #pragma unroll
    for (int k = 0; k < 8; k++) {
        const int tr = traceBase + trl0 + 8 * k;
        stage[k] = g4[tr * (T_DIM / 4) + tq];
    }

    // Per-trace scan state
    float vmax   = -3.4e38f;
    int   last   = -1000000;
    int   nclust = 0;
    int   curc   = 0x7fffffff;     // sentinel: no cluster open yet
    float cursum = 0.0f;  int curcnt = 0;
    int   bestc  = 0x7fffffff;
    float bestsum = 0.0f; int bestcnt = 0;

    #pragma unroll 1
    for (int tile = 0; tile < NTILE; tile++) {
        const int buf = tile & 1;

        // Stage -> shared (transposed): row = trace, col = t_local. STS.128.
        #pragma unroll
        for (int k = 0; k < 8; k++) {
            *reinterpret_cast<float4*>(&sh[buf][trl0 + 8 * k][4 * tq]) = stage[k];
        }
        __syncthreads();   // single barrier per tile (double buffer makes it sufficient)

        // Prefetch next tile (overlaps with scan below)
        if (tile + 1 < NTILE) {
            const int boff = (tile + 1) * (TT / 4) + tq;
            #pragma unroll
            for (int k = 0; k < 8; k++) {
                const int tr = traceBase + trl0 + 8 * k;
                stage[k] = g4[tr * (T_DIM / 4) + boff];
            }
        }

        // Scan own trace from shared (LDS.128, 8 per tile)
        const int tbase = tile * TT;
        #pragma unroll
        for (int j = 0; j < TT / 4; j++) {
            const float4 v = *reinterpret_cast<const float4*>(&sh[buf][tid][4 * j]);
            const int t = tbase + 4 * j;
            proc_step(v.x, t + 0, vmax, last, nclust, curc, cursum, curcnt, bestc, bestsum, bestcnt);
            proc_step(v.y, t + 1, vmax, last, nclust, curc, cursum, curcnt, bestc, bestsum, bestcnt);
            proc_step(v.z, t + 2, vmax, last, nclust, curc, cursum, curcnt, bestc, bestsum, bestcnt);
            proc_step(v.w, t + 3, vmax, last, nclust, curc, cursum, curcnt, bestc, bestsum, bestcnt);
        }
    }

    // Close final cluster
    if (curc < bestc) { bestc = curc; bestsum = cursum; bestcnt = curcnt; }

    // spike_output
    out_spike[myTrace] = (float)nclust;

    // Loss contribution
    const int b = myTrace / N_DIM;
    const int n = myTrace - b * N_DIM;
    float contrib = 0.0f;
    if (n == labels[b]) {
        if (nclust == 0) contrib = -vmax;                       // miss: -max(v)
    } else if (nclust > 0) {
        contrib = bestsum / fmaxf((float)bestcnt, 1.0f);        // false positive: mean of v>0 in smallest cluster
    }

    // Deterministic block tree reduction
    red[tid] = contrib;
    __syncthreads();
    #pragma unroll
    for (int off = TPB / 2; off > 0; off >>= 1) {
        if (tid < off) red[tid] += red[tid + off];
        __syncthreads();
    }
    if (tid == 0) g_partial[blockIdx.x] = red[0];
}

__global__ void __launch_bounds__(NBLOCKS)
stca_reduce(float* __restrict__ out)
{
    __shared__ float s[NBLOCKS];
    const int t = threadIdx.x;
    s[t] = g_partial[t];
    __syncthreads();
    #pragma unroll
    for (int off = NBLOCKS / 2; off > 0; off >>= 1) {
        if (t < off) s[t] += s[t + off];
        __syncthreads();
    }
    if (t == 0) out[0] = s[0];
}

extern "C" void kernel_launch(void* const* d_in, const int* in_sizes, int n_in,
                              void* d_out, int out_size)
{
    const float* vmem   = (const float*)d_in[0];
    // d_in[1] (vlastmem) is unused by the forward computation.
    const int*   labels = (const int*)d_in[2];
    float*       out    = (float*)d_out;

    stca_scan<<<NBLOCKS, TPB>>>(vmem, labels, out + 1);
    stca_reduce<<<1, NBLOCKS>>>(out);
}